// round 1
// baseline (speedup 1.0000x reference)
#include <cuda_runtime.h>
#include <math.h>

#define Bb 8
#define Ss 2048
#define Tt 512
#define Hh 1024
#define NH 16
#define DK 64

// ---- scratch (device globals: allocation-free) ----
__device__ float g_Q[Bb*Tt*Hh];        // 16.8 MB
__device__ float g_K[Bb*Ss*Hh];        // 67 MB
__device__ float g_V[Bb*Ss*Hh];        // 67 MB
__device__ float g_P[Bb*NH*Tt*Ss];     // 537 MB (scores -> probs in place)
__device__ float g_C[Bb*Tt*Hh];        // 16.8 MB (concat of AV)

// ============================================================
// SGEMM: C[M,N] = A[M,K] @ B[K,N] (+ bias). 128x128 tile, BK=8,
// 256 threads, 8x8 per thread.
// ============================================================
template<bool HAS_BIAS>
__global__ void __launch_bounds__(256) sgemm_kernel(
    const float* __restrict__ A, const float* __restrict__ Bm,
    const float* __restrict__ bias, float* __restrict__ C,
    int M, int N, int K)
{
    __shared__ float As[8][128];
    __shared__ float Bs[8][128];
    int tid = threadIdx.x;
    int tx = tid & 15, ty = tid >> 4;
    const float* Ablk = A + (size_t)blockIdx.y * 128 * K;
    const float* Bblk = Bm + blockIdx.x * 128;
    float acc[8][8] = {};

    int arow = tid >> 1;           // 0..127
    int acol = (tid & 1) * 4;      // 0 or 4
    int brow = tid >> 5;           // 0..7
    int bcol = (tid & 31) * 4;     // 0..124

    for (int k0 = 0; k0 < K; k0 += 8) {
        float4 av = *(const float4*)(Ablk + (size_t)arow * K + k0 + acol);
        As[acol+0][arow] = av.x; As[acol+1][arow] = av.y;
        As[acol+2][arow] = av.z; As[acol+3][arow] = av.w;
        *(float4*)&Bs[brow][bcol] = *(const float4*)(Bblk + (size_t)(k0 + brow) * N + bcol);
        __syncthreads();
        #pragma unroll
        for (int k = 0; k < 8; k++) {
            float a[8], b[8];
            *(float4*)&a[0] = *(const float4*)&As[k][ty*8];
            *(float4*)&a[4] = *(const float4*)&As[k][ty*8+4];
            *(float4*)&b[0] = *(const float4*)&Bs[k][tx*8];
            *(float4*)&b[4] = *(const float4*)&Bs[k][tx*8+4];
            #pragma unroll
            for (int i = 0; i < 8; i++)
                #pragma unroll
                for (int j = 0; j < 8; j++)
                    acc[i][j] = fmaf(a[i], b[j], acc[i][j]);
        }
        __syncthreads();
    }
    #pragma unroll
    for (int i = 0; i < 8; i++) {
        int row = blockIdx.y*128 + ty*8 + i;
        #pragma unroll
        for (int j = 0; j < 8; j += 4) {
            int col = blockIdx.x*128 + tx*8 + j;
            float4 v;
            v.x = acc[i][j+0]; v.y = acc[i][j+1];
            v.z = acc[i][j+2]; v.w = acc[i][j+3];
            if (HAS_BIAS) {
                v.x += bias[col]; v.y += bias[col+1];
                v.z += bias[col+2]; v.w += bias[col+3];
            }
            *(float4*)(C + (size_t)row * N + col) = v;
        }
    }
}

// ============================================================
// Scores: E[b,h,t,s] = Q[b,t,h,:]·K[b,s,h,:] / 8 + (1-mask[b,s])*(-1e20)
// 64(t) x 64(s) tile per block, K-dim = 64 fully in smem.
// ============================================================
__global__ void __launch_bounds__(256) scores_kernel(
    const float* __restrict__ Q, const float* __restrict__ Km,
    const int* __restrict__ mask, float* __restrict__ E)
{
    int bh = blockIdx.z, b = bh >> 4, h = bh & 15;
    int t0 = blockIdx.y * 64, s0 = blockIdx.x * 64;
    __shared__ float Qs[64][68];   // [d][t]
    __shared__ float Ks[64][68];   // [d][s]
    int tid = threadIdx.x, tx = tid & 15, ty = tid >> 4;

    int c = (tid & 15) * 4;
    #pragma unroll
    for (int i = 0; i < 4; i++) {
        int r = (tid >> 4) + i * 16;
        float4 qv = *(const float4*)(Q + (size_t)(b*Tt + t0 + r) * Hh + h*DK + c);
        Qs[c+0][r] = qv.x; Qs[c+1][r] = qv.y; Qs[c+2][r] = qv.z; Qs[c+3][r] = qv.w;
        float4 kv = *(const float4*)(Km + (size_t)(b*Ss + s0 + r) * Hh + h*DK + c);
        Ks[c+0][r] = kv.x; Ks[c+1][r] = kv.y; Ks[c+2][r] = kv.z; Ks[c+3][r] = kv.w;
    }
    __syncthreads();

    float acc[4][4] = {};
    #pragma unroll
    for (int d = 0; d < 64; d++) {
        float a[4], bv[4];
        *(float4*)a  = *(const float4*)&Qs[d][ty*4];
        *(float4*)bv = *(const float4*)&Ks[d][tx*4];
        #pragma unroll
        for (int i = 0; i < 4; i++)
            #pragma unroll
            for (int j = 0; j < 4; j++)
                acc[i][j] = fmaf(a[i], bv[j], acc[i][j]);
    }

    float negs[4];
    #pragma unroll
    for (int j = 0; j < 4; j++)
        negs[j] = (1.0f - (float)mask[b*Ss + s0 + tx*4 + j]) * (-1e20f);

    const float scale = 0.125f;   // 1/sqrt(64)
    #pragma unroll
    for (int i = 0; i < 4; i++) {
        size_t off = ((size_t)bh * Tt + t0 + ty*4 + i) * Ss + s0 + tx*4;
        float4 v;
        v.x = acc[i][0]*scale + negs[0];
        v.y = acc[i][1]*scale + negs[1];
        v.z = acc[i][2]*scale + negs[2];
        v.w = acc[i][3]*scale + negs[3];
        *(float4*)(E + off) = v;
    }
}

// ============================================================
// Softmax over s (2048) in place. One block per (b,h,t) row.
// ============================================================
__global__ void __launch_bounds__(256) softmax_kernel(float* __restrict__ E)
{
    float* p = E + (size_t)blockIdx.x * Ss;
    int tid = threadIdx.x;
    float v[8];
    float m = -3.0e38f;
    #pragma unroll
    for (int i = 0; i < 8; i++) { v[i] = p[tid + i*256]; m = fmaxf(m, v[i]); }

    __shared__ float red[256];
    red[tid] = m; __syncthreads();
    for (int s = 128; s > 0; s >>= 1) {
        if (tid < s) red[tid] = fmaxf(red[tid], red[tid+s]);
        __syncthreads();
    }
    m = red[0]; __syncthreads();

    float sum = 0.f;
    #pragma unroll
    for (int i = 0; i < 8; i++) { v[i] = __expf(v[i] - m); sum += v[i]; }
    red[tid] = sum; __syncthreads();
    for (int s = 128; s > 0; s >>= 1) {
        if (tid < s) red[tid] += red[tid+s];
        __syncthreads();
    }
    float inv = 1.0f / red[0];
    #pragma unroll
    for (int i = 0; i < 8; i++) p[tid + i*256] = v[i] * inv;
}

// ============================================================
// a_mean[b,t,s] = mean over h of P[b,h,t,s]
// ============================================================
__global__ void mean_kernel(const float* __restrict__ P, float* __restrict__ out)
{
    size_t idx = (size_t)blockIdx.x * blockDim.x + threadIdx.x;
    const size_t TS = (size_t)Tt * Ss;
    if (idx >= (size_t)Bb * TS) return;
    size_t b = idx / TS, r = idx - b * TS;
    float sum = 0.f;
    #pragma unroll
    for (int h = 0; h < NH; h++) sum += P[((size_t)(b*NH + h)) * TS + r];
    out[idx] = sum * (1.0f / 16.0f);
}

// ============================================================
// AV: C[b,t, h*64+d] = sum_s P[b,h,t,s] * V[b,s, h*64+d]
// 64(t) x 64(d) tile per block, loop s in chunks of 16.
// ============================================================
__global__ void __launch_bounds__(256) av_kernel(
    const float* __restrict__ P, const float* __restrict__ V,
    float* __restrict__ Cc)
{
    int bh = blockIdx.y, b = bh >> 4, h = bh & 15;
    int t0 = blockIdx.x * 64;
    __shared__ float Ps[16][68];   // [s][t]
    __shared__ float Vs[16][68];   // [s][d]
    int tid = threadIdx.x, tx = tid & 15, ty = tid >> 4;
    float acc[4][4] = {};

    const float* Pbase = P + ((size_t)bh * Tt + t0) * Ss;
    const float* Vbase = V + (size_t)b * Ss * Hh + h*DK;

    int pt = tid >> 2;             // 0..63 (t)
    int psc = (tid & 3) * 4;       // 0..12 (s chunk)
    int vsr = tid >> 4;            // 0..15 (s)
    int vdc = (tid & 15) * 4;      // 0..60 (d)

    for (int s0 = 0; s0 < Ss; s0 += 16) {
        float4 pv = *(const float4*)(Pbase + (size_t)pt * Ss + s0 + psc);
        Ps[psc+0][pt] = pv.x; Ps[psc+1][pt] = pv.y;
        Ps[psc+2][pt] = pv.z; Ps[psc+3][pt] = pv.w;
        *(float4*)&Vs[vsr][vdc] = *(const float4*)(Vbase + (size_t)(s0 + vsr) * Hh + vdc);
        __syncthreads();
        #pragma unroll
        for (int s = 0; s < 16; s++) {
            float a[4], bv[4];
            *(float4*)a  = *(const float4*)&Ps[s][ty*4];
            *(float4*)bv = *(const float4*)&Vs[s][tx*4];
            #pragma unroll
            for (int i = 0; i < 4; i++)
                #pragma unroll
                for (int j = 0; j < 4; j++)
                    acc[i][j] = fmaf(a[i], bv[j], acc[i][j]);
        }
        __syncthreads();
    }
    #pragma unroll
    for (int i = 0; i < 4; i++) {
        size_t off = (size_t)(b*Tt + t0 + ty*4 + i) * Hh + h*DK + tx*4;
        float4 v;
        v.x = acc[i][0]; v.y = acc[i][1]; v.z = acc[i][2]; v.w = acc[i][3];
        *(float4*)(Cc + off) = v;
    }
}

// ============================================================
extern "C" void kernel_launch(void* const* d_in, const int* in_sizes, int n_in,
                              void* d_out, int out_size)
{
    const float* hiddens = (const float*)d_in[0];
    const float* qh      = (const float*)d_in[1];
    const int*   mask    = (const int*)  d_in[2];
    const float* W_q     = (const float*)d_in[3];
    const float* b_q     = (const float*)d_in[4];
    const float* W_k     = (const float*)d_in[5];
    const float* W_v     = (const float*)d_in[6];
    const float* W_o     = (const float*)d_in[7];
    const float* b_o     = (const float*)d_in[8];
    float* out = (float*)d_out;

    float *pQ, *pK, *pV, *pP, *pC;
    cudaGetSymbolAddress((void**)&pQ, g_Q);
    cudaGetSymbolAddress((void**)&pK, g_K);
    cudaGetSymbolAddress((void**)&pV, g_V);
    cudaGetSymbolAddress((void**)&pP, g_P);
    cudaGetSymbolAddress((void**)&pC, g_C);

    // Projections
    sgemm_kernel<true ><<<dim3(8, 32),  256>>>(qh,      W_q, b_q,     pQ, Bb*Tt, Hh, Hh);
    sgemm_kernel<false><<<dim3(8, 128), 256>>>(hiddens, W_k, nullptr, pK, Bb*Ss, Hh, Hh);
    sgemm_kernel<false><<<dim3(8, 128), 256>>>(hiddens, W_v, nullptr, pV, Bb*Ss, Hh, Hh);

    // Scores + softmax
    scores_kernel<<<dim3(Ss/64, Tt/64, Bb*NH), 256>>>(pQ, pK, mask, pP);
    softmax_kernel<<<Bb*NH*Tt, 256>>>(pP);

    // Head-mean output (second output, after context)
    {
        size_t n = (size_t)Bb * Tt * Ss;
        mean_kernel<<<(unsigned)((n + 255) / 256), 256>>>(pP, out + (size_t)Bb*Tt*Hh);
    }

    // AV and output projection (context -> start of d_out)
    av_kernel<<<dim3(Tt/64, Bb*NH), 256>>>(pP, pV, pC);
    sgemm_kernel<true ><<<dim3(8, 32), 256>>>(pC, W_o, b_o, out, Bb*Tt, Hh, Hh);
}

// round 2
// speedup vs baseline: 2.7384x; 2.7384x over previous
#include <cuda_runtime.h>
#include <math.h>
#include <stdint.h>

#define Bb 8
#define Ss 2048
#define Tt 512
#define Hh 1024
#define NH 16
#define DK 64

// ---- scratch (device globals: allocation-free) ----
__device__ float g_Q[Bb*Tt*Hh];
__device__ float g_K[Bb*Ss*Hh];
__device__ float g_V[Bb*Ss*Hh];
__device__ float g_P[(size_t)Bb*NH*Tt*Ss];
__device__ float g_C[Bb*Tt*Hh];

// ------------------------------------------------------------
// tf32 helpers
// ------------------------------------------------------------
__device__ __forceinline__ uint32_t f2tf(float x) {
    uint32_t r;
    asm("cvt.rna.tf32.f32 %0, %1;" : "=r"(r) : "f"(x));
    return r;
}

__device__ __forceinline__ void mma_tf32(float* c, const uint32_t* a, const uint32_t* b) {
    asm volatile(
        "mma.sync.aligned.m16n8k8.row.col.f32.tf32.tf32.f32 "
        "{%0,%1,%2,%3}, {%4,%5,%6,%7}, {%8,%9}, {%0,%1,%2,%3};"
        : "+f"(c[0]), "+f"(c[1]), "+f"(c[2]), "+f"(c[3])
        : "r"(a[0]), "r"(a[1]), "r"(a[2]), "r"(a[3]),
          "r"(b[0]), "r"(b[1]));
}

// ============================================================
// Projection GEMM (tf32): C[M,N] = A[M,K] @ W[K,N] (+bias)
// block tile 128x128, BK=32, 256 threads, warp tile 64x32
// ============================================================
template<bool HAS_BIAS>
__global__ void __launch_bounds__(256) proj_tf32(
    const float* __restrict__ A, const float* __restrict__ W,
    const float* __restrict__ bias, float* __restrict__ C,
    int M, int N, int K)
{
    __shared__ uint32_t As[128*36];   // [m][k] ld 36
    __shared__ uint32_t Bs[32*136];   // [k][n] ld 136
    int tid = threadIdx.x;
    int lane = tid & 31, wid = tid >> 5;
    int lr = lane >> 2, lc = lane & 3;
    int wm = (wid >> 2) * 64;         // 0 / 64
    int wn = (wid & 3) * 32;          // 0..96
    int bx = blockIdx.x, by = blockIdx.y;

    float acc[2][4][4];               // acc[im half... actually 4 m-frags]
    float accm[4][4][4];
    #pragma unroll
    for (int i = 0; i < 4; i++)
        #pragma unroll
        for (int j = 0; j < 4; j++)
            #pragma unroll
            for (int q = 0; q < 4; q++) accm[i][j][q] = 0.f;
    (void)acc;

    const float* Ag = A + (size_t)by * 128 * K;
    const float* Bg = W + (size_t)bx * 128;

    for (int k0 = 0; k0 < K; k0 += 32) {
        __syncthreads();
        #pragma unroll
        for (int j = 0; j < 4; j++) {
            int id = tid + j*256;
            int r = id >> 3, c = (id & 7) * 4;
            float4 v = *(const float4*)(Ag + (size_t)r * K + k0 + c);
            uint32_t* d = &As[r*36 + c];
            d[0]=f2tf(v.x); d[1]=f2tf(v.y); d[2]=f2tf(v.z); d[3]=f2tf(v.w);
        }
        #pragma unroll
        for (int j = 0; j < 4; j++) {
            int id = tid + j*256;
            int r = id >> 5, c = (id & 31) * 4;
            float4 v = *(const float4*)(Bg + (size_t)(k0 + r) * N + c);
            uint32_t* d = &Bs[r*136 + c];
            d[0]=f2tf(v.x); d[1]=f2tf(v.y); d[2]=f2tf(v.z); d[3]=f2tf(v.w);
        }
        __syncthreads();

        #pragma unroll
        for (int ks = 0; ks < 32; ks += 8) {
            uint32_t a[4][4], b[4][2];
            #pragma unroll
            for (int im = 0; im < 4; im++) {
                int m = wm + im*16;
                a[im][0] = As[(m+lr  )*36 + ks+lc  ];
                a[im][1] = As[(m+lr+8)*36 + ks+lc  ];
                a[im][2] = As[(m+lr  )*36 + ks+lc+4];
                a[im][3] = As[(m+lr+8)*36 + ks+lc+4];
            }
            #pragma unroll
            for (int in_ = 0; in_ < 4; in_++) {
                int n = wn + in_*8;
                b[in_][0] = Bs[(ks+lc  )*136 + n+lr];
                b[in_][1] = Bs[(ks+lc+4)*136 + n+lr];
            }
            #pragma unroll
            for (int im = 0; im < 4; im++)
                #pragma unroll
                for (int in_ = 0; in_ < 4; in_++)
                    mma_tf32(accm[im][in_], a[im], b[in_]);
        }
    }

    #pragma unroll
    for (int im = 0; im < 4; im++) {
        #pragma unroll
        for (int in_ = 0; in_ < 4; in_++) {
            int r0 = by*128 + wm + im*16 + lr;
            int cb = bx*128 + wn + in_*8 + 2*lc;
            float2 v0, v1;
            v0.x = accm[im][in_][0]; v0.y = accm[im][in_][1];
            v1.x = accm[im][in_][2]; v1.y = accm[im][in_][3];
            if (HAS_BIAS) {
                v0.x += bias[cb]; v0.y += bias[cb+1];
                v1.x += bias[cb]; v1.y += bias[cb+1];
            }
            *(float2*)(C + (size_t)r0 * N + cb) = v0;
            *(float2*)(C + (size_t)(r0+8) * N + cb) = v1;
        }
    }
}

// ============================================================
// Scores (tf32): E[bh][t][s] = Q·K^T / 8 + mask
// block tile 128(t)x128(s), d=64 (2 chunks of 32)
// ============================================================
__global__ void __launch_bounds__(256) scores_tf32(
    const float* __restrict__ Q, const float* __restrict__ Km,
    const int* __restrict__ mask, float* __restrict__ E)
{
    __shared__ uint32_t Qs[128*36];   // [t][k]
    __shared__ uint32_t Ks[128*36];   // [s][k]
    int tid = threadIdx.x;
    int lane = tid & 31, wid = tid >> 5;
    int lr = lane >> 2, lc = lane & 3;
    int wm = (wid >> 2) * 64;
    int wn = (wid & 3) * 32;
    int bh = blockIdx.z, b = bh >> 4, h = bh & 15;
    int t0 = blockIdx.y * 128, s0 = blockIdx.x * 128;

    float accm[4][4][4];
    #pragma unroll
    for (int i = 0; i < 4; i++)
        #pragma unroll
        for (int j = 0; j < 4; j++)
            #pragma unroll
            for (int q = 0; q < 4; q++) accm[i][j][q] = 0.f;

    #pragma unroll
    for (int k0 = 0; k0 < 64; k0 += 32) {
        __syncthreads();
        #pragma unroll
        for (int j = 0; j < 4; j++) {
            int id = tid + j*256;
            int r = id >> 3, c = (id & 7) * 4;
            float4 v = *(const float4*)(Q + (size_t)(b*Tt + t0 + r) * Hh + h*DK + k0 + c);
            uint32_t* d = &Qs[r*36 + c];
            d[0]=f2tf(v.x); d[1]=f2tf(v.y); d[2]=f2tf(v.z); d[3]=f2tf(v.w);
        }
        #pragma unroll
        for (int j = 0; j < 4; j++) {
            int id = tid + j*256;
            int r = id >> 3, c = (id & 7) * 4;
            float4 v = *(const float4*)(Km + (size_t)(b*Ss + s0 + r) * Hh + h*DK + k0 + c);
            uint32_t* d = &Ks[r*36 + c];
            d[0]=f2tf(v.x); d[1]=f2tf(v.y); d[2]=f2tf(v.z); d[3]=f2tf(v.w);
        }
        __syncthreads();

        #pragma unroll
        for (int ks = 0; ks < 32; ks += 8) {
            uint32_t a[4][4], b2[4][2];
            #pragma unroll
            for (int im = 0; im < 4; im++) {
                int m = wm + im*16;
                a[im][0] = Qs[(m+lr  )*36 + ks+lc  ];
                a[im][1] = Qs[(m+lr+8)*36 + ks+lc  ];
                a[im][2] = Qs[(m+lr  )*36 + ks+lc+4];
                a[im][3] = Qs[(m+lr+8)*36 + ks+lc+4];
            }
            #pragma unroll
            for (int in_ = 0; in_ < 4; in_++) {
                int n = wn + in_*8;
                b2[in_][0] = Ks[(n+lr)*36 + ks+lc  ];
                b2[in_][1] = Ks[(n+lr)*36 + ks+lc+4];
            }
            #pragma unroll
            for (int im = 0; im < 4; im++)
                #pragma unroll
                for (int in_ = 0; in_ < 4; in_++)
                    mma_tf32(accm[im][in_], a[im], b2[in_]);
        }
    }

    const float scale = 0.125f;
    #pragma unroll
    for (int im = 0; im < 4; im++) {
        #pragma unroll
        for (int in_ = 0; in_ < 4; in_++) {
            int tg = t0 + wm + im*16 + lr;
            int sg = s0 + wn + in_*8 + 2*lc;
            float n0 = (1.0f - (float)mask[b*Ss + sg])   * (-1e20f);
            float n1 = (1.0f - (float)mask[b*Ss + sg+1]) * (-1e20f);
            float2 v0, v1;
            v0.x = accm[im][in_][0]*scale + n0;
            v0.y = accm[im][in_][1]*scale + n1;
            v1.x = accm[im][in_][2]*scale + n0;
            v1.y = accm[im][in_][3]*scale + n1;
            *(float2*)(E + ((size_t)bh*Tt + tg)*Ss + sg) = v0;
            *(float2*)(E + ((size_t)bh*Tt + tg + 8)*Ss + sg) = v1;
        }
    }
}

// ============================================================
// Fused softmax (over s, per head) + head-mean. Block per (b,t).
// ============================================================
__global__ void __launch_bounds__(256) softmax_mean(
    float* __restrict__ P, float* __restrict__ meanO)
{
    int b = blockIdx.x / Tt, t = blockIdx.x % Tt;
    int tid = threadIdx.x;
    int lane = tid & 31, wid = tid >> 5;
    __shared__ float sred[8];

    float msum[8];
    #pragma unroll
    for (int i = 0; i < 8; i++) msum[i] = 0.f;

    for (int h = 0; h < NH; h++) {
        float* p = P + ((size_t)(b*NH + h)*Tt + t)*Ss;
        float v[8];
        float m = -3.0e38f;
        #pragma unroll
        for (int i = 0; i < 8; i++) { v[i] = p[tid + i*256]; m = fmaxf(m, v[i]); }
        #pragma unroll
        for (int o = 16; o; o >>= 1) m = fmaxf(m, __shfl_xor_sync(0xffffffffu, m, o));
        if (lane == 0) sred[wid] = m;
        __syncthreads();
        m = sred[0];
        #pragma unroll
        for (int w = 1; w < 8; w++) m = fmaxf(m, sred[w]);
        __syncthreads();

        float sum = 0.f;
        #pragma unroll
        for (int i = 0; i < 8; i++) { v[i] = __expf(v[i] - m); sum += v[i]; }
        #pragma unroll
        for (int o = 16; o; o >>= 1) sum += __shfl_xor_sync(0xffffffffu, sum, o);
        if (lane == 0) sred[wid] = sum;
        __syncthreads();
        sum = 0.f;
        #pragma unroll
        for (int w = 0; w < 8; w++) sum += sred[w];
        __syncthreads();

        float inv = 1.0f / sum;
        #pragma unroll
        for (int i = 0; i < 8; i++) {
            float pv = v[i] * inv;
            p[tid + i*256] = pv;
            msum[i] += pv;
        }
    }

    float* mo = meanO + ((size_t)b*Tt + t)*Ss;
    #pragma unroll
    for (int i = 0; i < 8; i++) mo[tid + i*256] = msum[i] * (1.0f / 16.0f);
}

// ============================================================
// AV (tf32): C[b,t,h*64+d] = sum_s P[bh,t,s] * V[b,s,h*64+d]
// block tile 128(t)x64(d), BK=32, warp tile 32x32
// ============================================================
__global__ void __launch_bounds__(256) av_tf32(
    const float* __restrict__ P, const float* __restrict__ V,
    float* __restrict__ Cc)
{
    __shared__ uint32_t Ps[128*36];   // [t][s] ld 36
    __shared__ uint32_t Vs[32*72];    // [s][d] ld 72
    int tid = threadIdx.x;
    int lane = tid & 31, wid = tid >> 5;
    int lr = lane >> 2, lc = lane & 3;
    int wm = (wid >> 1) * 32;         // 0..96
    int wn = (wid & 1) * 32;          // 0 / 32
    int bh = blockIdx.y, b = bh >> 4, h = bh & 15;
    int t0 = blockIdx.x * 128;

    float accm[2][4][4];
    #pragma unroll
    for (int i = 0; i < 2; i++)
        #pragma unroll
        for (int j = 0; j < 4; j++)
            #pragma unroll
            for (int q = 0; q < 4; q++) accm[i][j][q] = 0.f;

    const float* Pbase = P + ((size_t)bh*Tt + t0)*Ss;
    const float* Vbase = V + (size_t)b*Ss*Hh + h*DK;

    for (int s0 = 0; s0 < Ss; s0 += 32) {
        __syncthreads();
        #pragma unroll
        for (int j = 0; j < 4; j++) {
            int id = tid + j*256;
            int r = id >> 3, c = (id & 7) * 4;
            float4 v = *(const float4*)(Pbase + (size_t)r*Ss + s0 + c);
            uint32_t* d = &Ps[r*36 + c];
            d[0]=f2tf(v.x); d[1]=f2tf(v.y); d[2]=f2tf(v.z); d[3]=f2tf(v.w);
        }
        #pragma unroll
        for (int j = 0; j < 2; j++) {
            int id = tid + j*256;
            int r = id >> 4, c = (id & 15) * 4;
            float4 v = *(const float4*)(Vbase + (size_t)(s0 + r)*Hh + c);
            uint32_t* d = &Vs[r*72 + c];
            d[0]=f2tf(v.x); d[1]=f2tf(v.y); d[2]=f2tf(v.z); d[3]=f2tf(v.w);
        }
        __syncthreads();

        #pragma unroll
        for (int ks = 0; ks < 32; ks += 8) {
            uint32_t a[2][4], b2[4][2];
            #pragma unroll
            for (int im = 0; im < 2; im++) {
                int m = wm + im*16;
                a[im][0] = Ps[(m+lr  )*36 + ks+lc  ];
                a[im][1] = Ps[(m+lr+8)*36 + ks+lc  ];
                a[im][2] = Ps[(m+lr  )*36 + ks+lc+4];
                a[im][3] = Ps[(m+lr+8)*36 + ks+lc+4];
            }
            #pragma unroll
            for (int in_ = 0; in_ < 4; in_++) {
                int n = wn + in_*8;
                b2[in_][0] = Vs[(ks+lc  )*72 + n+lr];
                b2[in_][1] = Vs[(ks+lc+4)*72 + n+lr];
            }
            #pragma unroll
            for (int im = 0; im < 2; im++)
                #pragma unroll
                for (int in_ = 0; in_ < 4; in_++)
                    mma_tf32(accm[im][in_], a[im], b2[in_]);
        }
    }

    #pragma unroll
    for (int im = 0; im < 2; im++) {
        #pragma unroll
        for (int in_ = 0; in_ < 4; in_++) {
            int r0 = t0 + wm + im*16 + lr;
            int cb = wn + in_*8 + 2*lc;
            float2 v0, v1;
            v0.x = accm[im][in_][0]; v0.y = accm[im][in_][1];
            v1.x = accm[im][in_][2]; v1.y = accm[im][in_][3];
            *(float2*)(Cc + (size_t)(b*Tt + r0)*Hh + h*DK + cb) = v0;
            *(float2*)(Cc + (size_t)(b*Tt + r0 + 8)*Hh + h*DK + cb) = v1;
        }
    }
}

// ============================================================
extern "C" void kernel_launch(void* const* d_in, const int* in_sizes, int n_in,
                              void* d_out, int out_size)
{
    const float* hiddens = (const float*)d_in[0];
    const float* qh      = (const float*)d_in[1];
    const int*   mask    = (const int*)  d_in[2];
    const float* W_q     = (const float*)d_in[3];
    const float* b_q     = (const float*)d_in[4];
    const float* W_k     = (const float*)d_in[5];
    const float* W_v     = (const float*)d_in[6];
    const float* W_o     = (const float*)d_in[7];
    const float* b_o     = (const float*)d_in[8];
    float* out = (float*)d_out;

    float *pQ, *pK, *pV, *pP, *pC;
    cudaGetSymbolAddress((void**)&pQ, g_Q);
    cudaGetSymbolAddress((void**)&pK, g_K);
    cudaGetSymbolAddress((void**)&pV, g_V);
    cudaGetSymbolAddress((void**)&pP, g_P);
    cudaGetSymbolAddress((void**)&pC, g_C);

    // Projections (tf32 tensor core)
    proj_tf32<true ><<<dim3(8, 32),  256>>>(qh,      W_q, b_q,     pQ, Bb*Tt, Hh, Hh);
    proj_tf32<false><<<dim3(8, 128), 256>>>(hiddens, W_k, nullptr, pK, Bb*Ss, Hh, Hh);
    proj_tf32<false><<<dim3(8, 128), 256>>>(hiddens, W_v, nullptr, pV, Bb*Ss, Hh, Hh);

    // Scores
    scores_tf32<<<dim3(Ss/128, Tt/128, Bb*NH), 256>>>(pQ, pK, mask, pP);

    // Softmax + head-mean (mean goes after context in d_out)
    softmax_mean<<<Bb*Tt, 256>>>(pP, out + (size_t)Bb*Tt*Hh);

    // AV and output projection
    av_tf32<<<dim3(Tt/128, Bb*NH), 256>>>(pP, pV, pC);
    proj_tf32<true ><<<dim3(8, 32), 256>>>(pC, W_o, b_o, out, Bb*Tt, Hh, Hh);
}

// round 3
// speedup vs baseline: 4.4550x; 1.6268x over previous
#include <cuda_runtime.h>
#include <cuda_fp16.h>
#include <math.h>
#include <stdint.h>

#define Bb 8
#define Ss 2048
#define Tt 512
#define Hh 1024
#define NH 16
#define DK 64

// ---- scratch (device globals: allocation-free) ----
__device__ __half g_Q[(size_t)Bb*Tt*Hh];
__device__ __half g_K[(size_t)Bb*Ss*Hh];
__device__ __half g_V[(size_t)Bb*Ss*Hh];
__device__ __half g_P[(size_t)Bb*NH*Tt*Ss];   // 268 MB fp16
__device__ __half g_C[(size_t)Bb*Tt*Hh];

// ------------------------------------------------------------
// helpers
// ------------------------------------------------------------
__device__ __forceinline__ uint32_t h2u(__half2 v) { return *(uint32_t*)&v; }

__device__ __forceinline__ void mma_f16(float* c, const uint32_t* a, const uint32_t* b) {
    asm volatile(
        "mma.sync.aligned.m16n8k16.row.col.f32.f16.f16.f32 "
        "{%0,%1,%2,%3}, {%4,%5,%6,%7}, {%8,%9}, {%0,%1,%2,%3};"
        : "+f"(c[0]), "+f"(c[1]), "+f"(c[2]), "+f"(c[3])
        : "r"(a[0]), "r"(a[1]), "r"(a[2]), "r"(a[3]),
          "r"(b[0]), "r"(b[1]));
}

__device__ __forceinline__ void ldsm_x4_t(uint32_t* r, uint32_t addr) {
    asm volatile("ldmatrix.sync.aligned.m8n8.x4.trans.shared.b16 {%0,%1,%2,%3}, [%4];"
        : "=r"(r[0]), "=r"(r[1]), "=r"(r[2]), "=r"(r[3]) : "r"(addr));
}

// Load two B fragments (n0, n0+8) for k0..k0+15 from row-major smem [k][n],
// row stride RS halves, via ldmatrix.trans.
__device__ __forceinline__ void ldB_pair(uint32_t* b0, uint32_t* b1,
                                         const __half* S, int RS, int k0, int n0, int lane) {
    int g = lane >> 3, r = lane & 7;
    int row = k0 + r + (g & 1) * 8;
    int col = n0 + (g >> 1) * 8;
    uint32_t addr = (uint32_t)__cvta_generic_to_shared(S + row * RS + col);
    uint32_t q[4];
    ldsm_x4_t(q, addr);
    b0[0] = q[0]; b0[1] = q[1];
    b1[0] = q[2]; b1[1] = q[3];
}

// ============================================================
// GEMM (fp16 mma): C[M,N] = scale*(A[M,K] @ W[K,N] (+bias))
// block 128x128, BK=32, 8 warps (2m x 4n), warp 64x32
// TA = float or __half input A; F16OUT selects output type.
// ============================================================
template<typename TA, bool F16OUT, bool HAS_BIAS>
__global__ void __launch_bounds__(256) gemm_f16(
    const TA* __restrict__ A, const float* __restrict__ W,
    const float* __restrict__ bias, void* __restrict__ Cout,
    int M, int N, int K, float scale)
{
    __shared__ __half As[128*40];
    __shared__ __half Bs[32*136];
    int tid = threadIdx.x, lane = tid & 31, wid = tid >> 5;
    int lr = lane >> 2, lc = lane & 3;
    int wm = (wid >> 2) * 64, wn = (wid & 3) * 32;
    int bx = blockIdx.x, by = blockIdx.y;

    float acc[4][4][4];
    #pragma unroll
    for (int i = 0; i < 4; i++)
        #pragma unroll
        for (int j = 0; j < 4; j++)
            #pragma unroll
            for (int q = 0; q < 4; q++) acc[i][j][q] = 0.f;

    const TA* Ag = A + (size_t)by * 128 * K;
    const float* Wg = W + bx * 128;

    for (int k0 = 0; k0 < K; k0 += 32) {
        // A tile 128x32 -> fp16 smem
        if (sizeof(TA) == 4) {
            #pragma unroll
            for (int j = 0; j < 4; j++) {
                int id = tid + j * 256;
                int r = id >> 3, c = (id & 7) * 4;
                float4 v = *(const float4*)((const float*)Ag + (size_t)r * K + k0 + c);
                uint2 u;
                u.x = h2u(__floats2half2_rn(v.x, v.y));
                u.y = h2u(__floats2half2_rn(v.z, v.w));
                *(uint2*)&As[r * 40 + c] = u;
            }
        } else {
            #pragma unroll
            for (int j = 0; j < 2; j++) {
                int id = tid + j * 256;
                int r = id >> 2, c = (id & 3) * 8;
                uint4 v = *(const uint4*)((const __half*)Ag + (size_t)r * K + k0 + c);
                *(uint4*)&As[r * 40 + c] = v;
            }
        }
        // W tile 32x128 -> fp16 smem [k][n]
        #pragma unroll
        for (int j = 0; j < 4; j++) {
            int id = tid + j * 256;
            int r = id >> 5, c = (id & 31) * 4;
            float4 v = *(const float4*)(Wg + (size_t)(k0 + r) * N + c);
            uint2 u;
            u.x = h2u(__floats2half2_rn(v.x, v.y));
            u.y = h2u(__floats2half2_rn(v.z, v.w));
            *(uint2*)&Bs[r * 136 + c] = u;
        }
        __syncthreads();

        #pragma unroll
        for (int ks = 0; ks < 32; ks += 16) {
            uint32_t a[4][4], b[4][2];
            #pragma unroll
            for (int im = 0; im < 4; im++) {
                int m = wm + im * 16;
                a[im][0] = *(uint32_t*)&As[(m + lr    ) * 40 + ks + 2*lc];
                a[im][1] = *(uint32_t*)&As[(m + lr + 8) * 40 + ks + 2*lc];
                a[im][2] = *(uint32_t*)&As[(m + lr    ) * 40 + ks + 8 + 2*lc];
                a[im][3] = *(uint32_t*)&As[(m + lr + 8) * 40 + ks + 8 + 2*lc];
            }
            ldB_pair(b[0], b[1], Bs, 136, ks, wn,      lane);
            ldB_pair(b[2], b[3], Bs, 136, ks, wn + 16, lane);
            #pragma unroll
            for (int im = 0; im < 4; im++)
                #pragma unroll
                for (int in_ = 0; in_ < 4; in_++)
                    mma_f16(acc[im][in_], a[im], b[in_]);
        }
        __syncthreads();
    }

    #pragma unroll
    for (int im = 0; im < 4; im++) {
        #pragma unroll
        for (int in_ = 0; in_ < 4; in_++) {
            int r0 = by * 128 + wm + im * 16 + lr;
            int cb = bx * 128 + wn + in_ * 8 + 2 * lc;
            float b0 = HAS_BIAS ? bias[cb] : 0.f;
            float b1 = HAS_BIAS ? bias[cb + 1] : 0.f;
            float x0 = (acc[im][in_][0] + b0) * scale;
            float x1 = (acc[im][in_][1] + b1) * scale;
            float x2 = (acc[im][in_][2] + b0) * scale;
            float x3 = (acc[im][in_][3] + b1) * scale;
            if (F16OUT) {
                __half* C = (__half*)Cout;
                *(__half2*)(C + (size_t)r0 * N + cb)       = __floats2half2_rn(x0, x1);
                *(__half2*)(C + (size_t)(r0 + 8) * N + cb) = __floats2half2_rn(x2, x3);
            } else {
                float* C = (float*)Cout;
                *(float2*)(C + (size_t)r0 * N + cb)       = make_float2(x0, x1);
                *(float2*)(C + (size_t)(r0 + 8) * N + cb) = make_float2(x2, x3);
            }
        }
    }
}

// ============================================================
// Scores (fp16 mma): E[bh][t][s] = Q·K^T (Q pre-scaled); masked -> -30000
// block 128t x 128s, d=64 loaded once. 8 warps (2m x 4n), warp 64x32.
// ============================================================
__global__ void __launch_bounds__(256) scores_f16(
    const __half* __restrict__ Q, const __half* __restrict__ Kh,
    const int* __restrict__ mask, __half* __restrict__ E)
{
    __shared__ __half Qs[128*72];
    __shared__ __half Ks[128*72];
    int tid = threadIdx.x, lane = tid & 31, wid = tid >> 5;
    int lr = lane >> 2, lc = lane & 3;
    int wm = (wid >> 2) * 64, wn = (wid & 3) * 32;
    int bh = blockIdx.z, b = bh >> 4, h = bh & 15;
    int t0 = blockIdx.y * 128, s0 = blockIdx.x * 128;

    #pragma unroll
    for (int j = 0; j < 4; j++) {
        int id = tid + j * 256;
        int r = id >> 3, c = (id & 7) * 8;
        *(uint4*)&Qs[r * 72 + c] =
            *(const uint4*)(Q + (size_t)(b * Tt + t0 + r) * Hh + h * DK + c);
        *(uint4*)&Ks[r * 72 + c] =
            *(const uint4*)(Kh + (size_t)(b * Ss + s0 + r) * Hh + h * DK + c);
    }
    __syncthreads();

    float acc[4][4][4];
    #pragma unroll
    for (int i = 0; i < 4; i++)
        #pragma unroll
        for (int j = 0; j < 4; j++)
            #pragma unroll
            for (int q = 0; q < 4; q++) acc[i][j][q] = 0.f;

    #pragma unroll
    for (int ks = 0; ks < 64; ks += 16) {
        uint32_t a[4][4], b2[4][2];
        #pragma unroll
        for (int im = 0; im < 4; im++) {
            int m = wm + im * 16;
            a[im][0] = *(uint32_t*)&Qs[(m + lr    ) * 72 + ks + 2*lc];
            a[im][1] = *(uint32_t*)&Qs[(m + lr + 8) * 72 + ks + 2*lc];
            a[im][2] = *(uint32_t*)&Qs[(m + lr    ) * 72 + ks + 8 + 2*lc];
            a[im][3] = *(uint32_t*)&Qs[(m + lr + 8) * 72 + ks + 8 + 2*lc];
        }
        #pragma unroll
        for (int in_ = 0; in_ < 4; in_++) {
            int n = wn + in_ * 8;
            b2[in_][0] = *(uint32_t*)&Ks[(n + lr) * 72 + ks + 2*lc];
            b2[in_][1] = *(uint32_t*)&Ks[(n + lr) * 72 + ks + 8 + 2*lc];
        }
        #pragma unroll
        for (int im = 0; im < 4; im++)
            #pragma unroll
            for (int in_ = 0; in_ < 4; in_++)
                mma_f16(acc[im][in_], a[im], b2[in_]);
    }

    #pragma unroll
    for (int in_ = 0; in_ < 4; in_++) {
        int sg = s0 + wn + in_ * 8 + 2 * lc;
        int m0v = mask[b * Ss + sg];
        int m1v = mask[b * Ss + sg + 1];
        #pragma unroll
        for (int im = 0; im < 4; im++) {
            int tg = t0 + wm + im * 16 + lr;
            float x0 = m0v ? acc[im][in_][0] : -30000.f;
            float x1 = m1v ? acc[im][in_][1] : -30000.f;
            float x2 = m0v ? acc[im][in_][2] : -30000.f;
            float x3 = m1v ? acc[im][in_][3] : -30000.f;
            *(__half2*)(E + ((size_t)bh * Tt + tg) * Ss + sg)       = __floats2half2_rn(x0, x1);
            *(__half2*)(E + ((size_t)bh * Tt + tg + 8) * Ss + sg)   = __floats2half2_rn(x2, x3);
        }
    }
}

// ============================================================
// Fused softmax (over s, per head) + head-mean. Block per (b,t).
// ============================================================
__global__ void __launch_bounds__(256) softmax_mean(
    __half* __restrict__ P, float* __restrict__ meanO)
{
    int b = blockIdx.x / Tt, t = blockIdx.x % Tt;
    int tid = threadIdx.x;
    int lane = tid & 31, wid = tid >> 5;
    __shared__ float sred[8];

    float msum[8];
    #pragma unroll
    for (int i = 0; i < 8; i++) msum[i] = 0.f;

    for (int h = 0; h < NH; h++) {
        __half2* p = (__half2*)(P + ((size_t)(b * NH + h) * Tt + t) * Ss);
        float v[8];
        float m = -3.0e38f;
        #pragma unroll
        for (int i = 0; i < 4; i++) {
            float2 f = __half22float2(p[tid + i * 256]);
            v[2*i] = f.x; v[2*i+1] = f.y;
            m = fmaxf(m, fmaxf(f.x, f.y));
        }
        #pragma unroll
        for (int o = 16; o; o >>= 1) m = fmaxf(m, __shfl_xor_sync(0xffffffffu, m, o));
        if (lane == 0) sred[wid] = m;
        __syncthreads();
        m = sred[0];
        #pragma unroll
        for (int w = 1; w < 8; w++) m = fmaxf(m, sred[w]);
        __syncthreads();

        float sum = 0.f;
        #pragma unroll
        for (int i = 0; i < 8; i++) { v[i] = __expf(v[i] - m); sum += v[i]; }
        #pragma unroll
        for (int o = 16; o; o >>= 1) sum += __shfl_xor_sync(0xffffffffu, sum, o);
        if (lane == 0) sred[wid] = sum;
        __syncthreads();
        sum = 0.f;
        #pragma unroll
        for (int w = 0; w < 8; w++) sum += sred[w];
        __syncthreads();

        float inv = 1.0f / sum;
        #pragma unroll
        for (int i = 0; i < 4; i++) {
            float p0 = v[2*i] * inv, p1 = v[2*i+1] * inv;
            p[tid + i * 256] = __floats2half2_rn(p0, p1);
            msum[2*i] += p0; msum[2*i+1] += p1;
        }
    }

    float* mo = meanO + ((size_t)b * Tt + t) * Ss;
    #pragma unroll
    for (int i = 0; i < 4; i++) {
        float2 v2 = make_float2(msum[2*i] * (1.f/16.f), msum[2*i+1] * (1.f/16.f));
        *(float2*)(mo + (tid + i * 256) * 2) = v2;
    }
}

// ============================================================
// AV (fp16 mma): C[b,t,h*64+d] = sum_s P[bh,t,s] * V[b,s,h*64+d]
// block 128t x 64d, k-chunk 64. 8 warps (4m x 2n), warp 32x32.
// ============================================================
__global__ void __launch_bounds__(256) av_f16(
    const __half* __restrict__ P, const __half* __restrict__ V,
    __half* __restrict__ Cc)
{
    __shared__ __half Ps[128*72];
    __shared__ __half Vs[64*72];
    int tid = threadIdx.x, lane = tid & 31, wid = tid >> 5;
    int lr = lane >> 2, lc = lane & 3;
    int wm = (wid >> 1) * 32, wn = (wid & 1) * 32;
    int bh = blockIdx.y, b = bh >> 4, h = bh & 15;
    int t0 = blockIdx.x * 128;

    float acc[2][4][4];
    #pragma unroll
    for (int i = 0; i < 2; i++)
        #pragma unroll
        for (int j = 0; j < 4; j++)
            #pragma unroll
            for (int q = 0; q < 4; q++) acc[i][j][q] = 0.f;

    const __half* Pbase = P + ((size_t)bh * Tt + t0) * Ss;
    const __half* Vbase = V + (size_t)b * Ss * Hh + h * DK;

    for (int s0 = 0; s0 < Ss; s0 += 64) {
        #pragma unroll
        for (int j = 0; j < 4; j++) {
            int id = tid + j * 256;
            int r = id >> 3, c = (id & 7) * 8;
            *(uint4*)&Ps[r * 72 + c] = *(const uint4*)(Pbase + (size_t)r * Ss + s0 + c);
        }
        #pragma unroll
        for (int j = 0; j < 2; j++) {
            int id = tid + j * 256;
            int r = id >> 3, c = (id & 7) * 8;
            *(uint4*)&Vs[r * 72 + c] = *(const uint4*)(Vbase + (size_t)(s0 + r) * Hh + c);
        }
        __syncthreads();

        #pragma unroll
        for (int ks = 0; ks < 64; ks += 16) {
            uint32_t a[2][4], b2[4][2];
            #pragma unroll
            for (int im = 0; im < 2; im++) {
                int m = wm + im * 16;
                a[im][0] = *(uint32_t*)&Ps[(m + lr    ) * 72 + ks + 2*lc];
                a[im][1] = *(uint32_t*)&Ps[(m + lr + 8) * 72 + ks + 2*lc];
                a[im][2] = *(uint32_t*)&Ps[(m + lr    ) * 72 + ks + 8 + 2*lc];
                a[im][3] = *(uint32_t*)&Ps[(m + lr + 8) * 72 + ks + 8 + 2*lc];
            }
            ldB_pair(b2[0], b2[1], Vs, 72, ks, wn,      lane);
            ldB_pair(b2[2], b2[3], Vs, 72, ks, wn + 16, lane);
            #pragma unroll
            for (int im = 0; im < 2; im++)
                #pragma unroll
                for (int in_ = 0; in_ < 4; in_++)
                    mma_f16(acc[im][in_], a[im], b2[in_]);
        }
        __syncthreads();
    }

    #pragma unroll
    for (int im = 0; im < 2; im++) {
        #pragma unroll
        for (int in_ = 0; in_ < 4; in_++) {
            int r0 = t0 + wm + im * 16 + lr;
            int cb = wn + in_ * 8 + 2 * lc;
            *(__half2*)(Cc + (size_t)(b * Tt + r0) * Hh + h * DK + cb) =
                __floats2half2_rn(acc[im][in_][0], acc[im][in_][1]);
            *(__half2*)(Cc + (size_t)(b * Tt + r0 + 8) * Hh + h * DK + cb) =
                __floats2half2_rn(acc[im][in_][2], acc[im][in_][3]);
        }
    }
}

// ============================================================
extern "C" void kernel_launch(void* const* d_in, const int* in_sizes, int n_in,
                              void* d_out, int out_size)
{
    const float* hiddens = (const float*)d_in[0];
    const float* qh      = (const float*)d_in[1];
    const int*   mask    = (const int*)  d_in[2];
    const float* W_q     = (const float*)d_in[3];
    const float* b_q     = (const float*)d_in[4];
    const float* W_k     = (const float*)d_in[5];
    const float* W_v     = (const float*)d_in[6];
    const float* W_o     = (const float*)d_in[7];
    const float* b_o     = (const float*)d_in[8];
    float* out = (float*)d_out;

    __half *pQ, *pK, *pV, *pP, *pC;
    cudaGetSymbolAddress((void**)&pQ, g_Q);
    cudaGetSymbolAddress((void**)&pK, g_K);
    cudaGetSymbolAddress((void**)&pV, g_V);
    cudaGetSymbolAddress((void**)&pP, g_P);
    cudaGetSymbolAddress((void**)&pC, g_C);

    // Projections (fp16 mma; Q gets 1/8 scale folded in)
    gemm_f16<float, true, true ><<<dim3(8, 32),  256>>>(qh,      W_q, b_q,     pQ, Bb*Tt, Hh, Hh, 0.125f);
    gemm_f16<float, true, false><<<dim3(8, 128), 256>>>(hiddens, W_k, nullptr, pK, Bb*Ss, Hh, Hh, 1.0f);
    gemm_f16<float, true, false><<<dim3(8, 128), 256>>>(hiddens, W_v, nullptr, pV, Bb*Ss, Hh, Hh, 1.0f);

    // Scores (writes fp16 P with masked = -30000)
    scores_f16<<<dim3(Ss/128, Tt/128, Bb*NH), 256>>>(pQ, pK, mask, pP);

    // Softmax + head-mean
    softmax_mean<<<Bb*Tt, 256>>>(pP, out + (size_t)Bb*Tt*Hh);

    // AV and output projection
    av_f16<<<dim3(Tt/128, Bb*NH), 256>>>(pP, pV, pC);
    gemm_f16<__half, false, true><<<dim3(8, 32), 256>>>(pC, W_o, b_o, out, Bb*Tt, Hh, Hh, 1.0f);
}

// round 4
// speedup vs baseline: 5.4573x; 1.2250x over previous
#include <cuda_runtime.h>
#include <cuda_fp16.h>
#include <math.h>
#include <stdint.h>

#define Bb 8
#define Ss 2048
#define Tt 512
#define Hh 1024
#define NH 16
#define DK 64

// ---- scratch (device globals: allocation-free) ----
__device__ __half g_H [(size_t)Bb*Ss*Hh];   // hiddens fp16
__device__ __half g_QH[(size_t)Bb*Tt*Hh];   // query hiddens fp16
__device__ __half g_Wq[Hh*Hh], g_Wk[Hh*Hh], g_Wv[Hh*Hh], g_Wo[Hh*Hh];
__device__ __half g_Q [(size_t)Bb*Tt*Hh];
__device__ __half g_K [(size_t)Bb*Ss*Hh];
__device__ __half g_V [(size_t)Bb*Ss*Hh];
__device__ __half g_P [(size_t)Bb*NH*Tt*Ss];  // 268 MB (probs)
__device__ __half g_C [(size_t)Bb*Tt*Hh];

// ------------------------------------------------------------
__device__ __forceinline__ uint32_t h2u(__half2 v) { return *(uint32_t*)&v; }

__device__ __forceinline__ void mma_f16(float* c, const uint32_t* a, const uint32_t* b) {
    asm volatile(
        "mma.sync.aligned.m16n8k16.row.col.f32.f16.f16.f32 "
        "{%0,%1,%2,%3}, {%4,%5,%6,%7}, {%8,%9}, {%0,%1,%2,%3};"
        : "+f"(c[0]), "+f"(c[1]), "+f"(c[2]), "+f"(c[3])
        : "r"(a[0]), "r"(a[1]), "r"(a[2]), "r"(a[3]),
          "r"(b[0]), "r"(b[1]));
}

__device__ __forceinline__ void cpa16(void* dst, const void* src) {
    uint32_t d = (uint32_t)__cvta_generic_to_shared(dst);
    asm volatile("cp.async.cg.shared.global [%0], [%1], 16;" :: "r"(d), "l"(src));
}
__device__ __forceinline__ void cp_commit() { asm volatile("cp.async.commit_group;"); }
template<int N_> __device__ __forceinline__ void cp_wait() {
    asm volatile("cp.async.wait_group %0;" :: "n"(N_));
}

__device__ __forceinline__ void ldsm_x4_t(uint32_t* r, uint32_t addr) {
    asm volatile("ldmatrix.sync.aligned.m8n8.x4.trans.shared.b16 {%0,%1,%2,%3}, [%4];"
        : "=r"(r[0]), "=r"(r[1]), "=r"(r[2]), "=r"(r[3]) : "r"(addr));
}
// two B fragments (n0, n0+8) for k0..k0+15 from row-major smem [k][n]
__device__ __forceinline__ void ldB_pair(uint32_t* b0, uint32_t* b1,
                                         const __half* S, int RS, int k0, int n0, int lane) {
    int g = lane >> 3, r = lane & 7;
    int row = k0 + r + (g & 1) * 8;
    int col = n0 + (g >> 1) * 8;
    uint32_t addr = (uint32_t)__cvta_generic_to_shared(S + row * RS + col);
    uint32_t q[4];
    ldsm_x4_t(q, addr);
    b0[0] = q[0]; b0[1] = q[1];
    b1[0] = q[2]; b1[1] = q[3];
}

// ============================================================
// fp32 -> fp16 convert (vectorized x4)
// ============================================================
__global__ void f2h4(const float* __restrict__ in, __half* __restrict__ out, int n4) {
    int i = blockIdx.x * blockDim.x + threadIdx.x;
    if (i < n4) {
        float4 v = ((const float4*)in)[i];
        uint2 u;
        u.x = h2u(__floats2half2_rn(v.x, v.y));
        u.y = h2u(__floats2half2_rn(v.z, v.w));
        ((uint2*)out)[i] = u;
    }
}

// ============================================================
// fp16 GEMM: C[M,N] = scale*(A[M,K]@W[K,N] + bias)
// 128x128 tile, BK=64, cp.async double-buffered, 8 warps 64x32
// ============================================================
template<bool F16OUT, bool HAS_BIAS>
__global__ void __launch_bounds__(256) gemm16(
    const __half* __restrict__ A, const __half* __restrict__ W,
    const float* __restrict__ bias, void* __restrict__ Cout,
    int M, int N, int K, float scale)
{
    extern __shared__ __half smx[];
    __half* As = smx;                  // 2 x [128][72]
    __half* Bs = smx + 2 * 128 * 72;   // 2 x [64][136]
    int tid = threadIdx.x, lane = tid & 31, wid = tid >> 5;
    int lr = lane >> 2, lc = lane & 3;
    int wm = (wid >> 2) * 64, wn = (wid & 3) * 32;
    int bx = blockIdx.x, by = blockIdx.y;

    const __half* Ag = A + (size_t)by * 128 * K;
    const __half* Wg = W + bx * 128;

    float acc[4][4][4];
    #pragma unroll
    for (int i = 0; i < 4; i++)
        #pragma unroll
        for (int j = 0; j < 4; j++)
            #pragma unroll
            for (int q = 0; q < 4; q++) acc[i][j][q] = 0.f;

    auto loadAB = [&](int buf, int k0) {
        __half* Ab = As + buf * 128 * 72;
        __half* Bb2 = Bs + buf * 64 * 136;
        #pragma unroll
        for (int j = 0; j < 4; j++) {
            int id = tid + j * 256;
            int r = id >> 3, c = (id & 7) * 8;
            cpa16(Ab + r * 72 + c, Ag + (size_t)r * K + k0 + c);
        }
        #pragma unroll
        for (int j = 0; j < 4; j++) {
            int id = tid + j * 256;
            int r = id >> 4, c = (id & 15) * 8;
            cpa16(Bb2 + r * 136 + c, Wg + (size_t)(k0 + r) * N + c);
        }
        cp_commit();
    };

    int nit = K / 64;
    loadAB(0, 0);
    for (int it = 0; it < nit; it++) {
        if (it + 1 < nit) loadAB((it + 1) & 1, (it + 1) * 64);
        if (it + 1 < nit) cp_wait<1>(); else cp_wait<0>();
        __syncthreads();
        const __half* Ab = As + (it & 1) * 128 * 72;
        const __half* Bb2 = Bs + (it & 1) * 64 * 136;
        #pragma unroll
        for (int ks = 0; ks < 64; ks += 16) {
            uint32_t a[4][4], b[4][2];
            #pragma unroll
            for (int im = 0; im < 4; im++) {
                int m = wm + im * 16;
                a[im][0] = *(const uint32_t*)&Ab[(m + lr    ) * 72 + ks + 2*lc];
                a[im][1] = *(const uint32_t*)&Ab[(m + lr + 8) * 72 + ks + 2*lc];
                a[im][2] = *(const uint32_t*)&Ab[(m + lr    ) * 72 + ks + 8 + 2*lc];
                a[im][3] = *(const uint32_t*)&Ab[(m + lr + 8) * 72 + ks + 8 + 2*lc];
            }
            ldB_pair(b[0], b[1], Bb2, 136, ks, wn,      lane);
            ldB_pair(b[2], b[3], Bb2, 136, ks, wn + 16, lane);
            #pragma unroll
            for (int im = 0; im < 4; im++)
                #pragma unroll
                for (int in_ = 0; in_ < 4; in_++)
                    mma_f16(acc[im][in_], a[im], b[in_]);
        }
        __syncthreads();
    }

    #pragma unroll
    for (int im = 0; im < 4; im++) {
        #pragma unroll
        for (int in_ = 0; in_ < 4; in_++) {
            int r0 = by * 128 + wm + im * 16 + lr;
            int cb = bx * 128 + wn + in_ * 8 + 2 * lc;
            float b0 = HAS_BIAS ? bias[cb] : 0.f;
            float b1 = HAS_BIAS ? bias[cb + 1] : 0.f;
            float x0 = (acc[im][in_][0] + b0) * scale;
            float x1 = (acc[im][in_][1] + b1) * scale;
            float x2 = (acc[im][in_][2] + b0) * scale;
            float x3 = (acc[im][in_][3] + b1) * scale;
            if (F16OUT) {
                __half* C = (__half*)Cout;
                *(__half2*)(C + (size_t)r0 * N + cb)       = __floats2half2_rn(x0, x1);
                *(__half2*)(C + (size_t)(r0 + 8) * N + cb) = __floats2half2_rn(x2, x3);
            } else {
                float* C = (float*)Cout;
                *(float2*)(C + (size_t)r0 * N + cb)       = make_float2(x0, x1);
                *(float2*)(C + (size_t)(r0 + 8) * N + cb) = make_float2(x2, x3);
            }
        }
    }
}

// ============================================================
// Fused scores + softmax. Block = (bh, 32 t-rows); full s=2048 row
// in smem; K streamed via cp.async; writes normalized P once.
// ============================================================
__global__ void __launch_bounds__(256) scores_softmax(
    const __half* __restrict__ Q, const __half* __restrict__ Kg,
    const int* __restrict__ mask, __half* __restrict__ P)
{
    extern __shared__ __half sms[];
    __half* Es = sms;                 // [32][2056]
    __half* Ks = sms + 32 * 2056;     // 2 x [128][72]
    __half* Qs = Ks + 2 * 128 * 72;   // [32][72]

    int tid = threadIdx.x, lane = tid & 31, wid = tid >> 5;
    int lr = lane >> 2, lc = lane & 3;
    int bh = blockIdx.y, b = bh >> 4, h = bh & 15;
    int t0 = blockIdx.x * 32;
    int n0 = wid * 16;

    // Q tile [32][64]
    {
        int r = tid >> 3, c = (tid & 7) * 8;
        *(uint4*)&Qs[r * 72 + c] =
            *(const uint4*)(Q + (size_t)(b * Tt + t0 + r) * Hh + h * DK + c);
    }

    auto loadK = [&](int buf, int s0) {
        __half* Kb = Ks + buf * 128 * 72;
        #pragma unroll
        for (int j = 0; j < 4; j++) {
            int id = tid + j * 256;
            int r = id >> 3, c = (id & 7) * 8;
            cpa16(Kb + r * 72 + c, Kg + (size_t)(b * Ss + s0 + r) * Hh + h * DK + c);
        }
        cp_commit();
    };

    loadK(0, 0);
    for (int it = 0; it < 16; it++) {
        if (it + 1 < 16) loadK((it + 1) & 1, (it + 1) * 128);
        if (it + 1 < 16) cp_wait<1>(); else cp_wait<0>();
        __syncthreads();
        const __half* Kb = Ks + (it & 1) * 128 * 72;
        int s0 = it * 128;

        float acc[2][2][4];
        #pragma unroll
        for (int i = 0; i < 2; i++)
            #pragma unroll
            for (int j = 0; j < 2; j++)
                #pragma unroll
                for (int q = 0; q < 4; q++) acc[i][j][q] = 0.f;

        #pragma unroll
        for (int ks = 0; ks < 64; ks += 16) {
            uint32_t a[2][4], bf[2][2];
            #pragma unroll
            for (int im = 0; im < 2; im++) {
                int m = im * 16;
                a[im][0] = *(const uint32_t*)&Qs[(m + lr    ) * 72 + ks + 2*lc];
                a[im][1] = *(const uint32_t*)&Qs[(m + lr + 8) * 72 + ks + 2*lc];
                a[im][2] = *(const uint32_t*)&Qs[(m + lr    ) * 72 + ks + 8 + 2*lc];
                a[im][3] = *(const uint32_t*)&Qs[(m + lr + 8) * 72 + ks + 8 + 2*lc];
            }
            #pragma unroll
            for (int in_ = 0; in_ < 2; in_++) {
                int n = n0 + in_ * 8;
                bf[in_][0] = *(const uint32_t*)&Kb[(n + lr) * 72 + ks + 2*lc];
                bf[in_][1] = *(const uint32_t*)&Kb[(n + lr) * 72 + ks + 8 + 2*lc];
            }
            #pragma unroll
            for (int im = 0; im < 2; im++)
                #pragma unroll
                for (int in_ = 0; in_ < 2; in_++)
                    mma_f16(acc[im][in_], a[im], bf[in_]);
        }

        #pragma unroll
        for (int im = 0; im < 2; im++) {
            #pragma unroll
            for (int in_ = 0; in_ < 2; in_++) {
                int t = im * 16 + lr;
                int s = s0 + n0 + in_ * 8 + 2 * lc;
                *(__half2*)&Es[t * 2056 + s] =
                    __floats2half2_rn(acc[im][in_][0], acc[im][in_][1]);
                *(__half2*)&Es[(t + 8) * 2056 + s] =
                    __floats2half2_rn(acc[im][in_][2], acc[im][in_][3]);
            }
        }
        __syncthreads();
    }

    // ---- softmax: each warp handles 4 rows ----
    const int* mrow = mask + b * Ss;
    const __half minus3e4 = __float2half(-30000.f);
    for (int rr = 0; rr < 4; rr++) {
        int r = wid * 4 + rr;
        uint4 E[8];
        float mx = -3.0e38f;
        #pragma unroll
        for (int i = 0; i < 8; i++) {
            int s = i * 256 + lane * 8;
            E[i] = *(uint4*)&Es[r * 2056 + s];
            int4 m0 = *(const int4*)&mrow[s];
            int4 m1 = *(const int4*)&mrow[s + 4];
            __half* hp = (__half*)&E[i];
            if (!m0.x) hp[0] = minus3e4;
            if (!m0.y) hp[1] = minus3e4;
            if (!m0.z) hp[2] = minus3e4;
            if (!m0.w) hp[3] = minus3e4;
            if (!m1.x) hp[4] = minus3e4;
            if (!m1.y) hp[5] = minus3e4;
            if (!m1.z) hp[6] = minus3e4;
            if (!m1.w) hp[7] = minus3e4;
            __half2* h2p = (__half2*)&E[i];
            #pragma unroll
            for (int j = 0; j < 4; j++) {
                float2 f = __half22float2(h2p[j]);
                mx = fmaxf(mx, fmaxf(f.x, f.y));
            }
        }
        #pragma unroll
        for (int o = 16; o; o >>= 1) mx = fmaxf(mx, __shfl_xor_sync(0xffffffffu, mx, o));

        float sum = 0.f;
        #pragma unroll
        for (int i = 0; i < 8; i++) {
            __half2* h2p = (__half2*)&E[i];
            #pragma unroll
            for (int j = 0; j < 4; j++) {
                float2 f = __half22float2(h2p[j]);
                float e0 = __expf(f.x - mx), e1 = __expf(f.y - mx);
                sum += e0 + e1;
                h2p[j] = __floats2half2_rn(e0, e1);
            }
        }
        #pragma unroll
        for (int o = 16; o; o >>= 1) sum += __shfl_xor_sync(0xffffffffu, sum, o);
        float inv = 1.0f / sum;

        __half* Pd = P + ((size_t)bh * Tt + t0 + r) * Ss;
        #pragma unroll
        for (int i = 0; i < 8; i++) {
            __half2* h2p = (__half2*)&E[i];
            #pragma unroll
            for (int j = 0; j < 4; j++) {
                float2 f = __half22float2(h2p[j]);
                h2p[j] = __floats2half2_rn(f.x * inv, f.y * inv);
            }
            int s = i * 256 + lane * 8;
            *(uint4*)(Pd + s) = E[i];
        }
    }
}

// ============================================================
// mean over heads: out[b,t,s] = (1/16) sum_h P[b,h,t,s]
// ============================================================
__global__ void mean_kernel(const __half* __restrict__ P, float* __restrict__ out)
{
    const size_t TS = (size_t)Tt * Ss;
    size_t idx = (size_t)blockIdx.x * blockDim.x + threadIdx.x;   // x8 elems
    size_t base = idx * 8;
    if (base >= (size_t)Bb * TS) return;
    size_t b = base / TS, r = base - b * TS;
    float s[8] = {0,0,0,0,0,0,0,0};
    #pragma unroll
    for (int h = 0; h < NH; h++) {
        uint4 v = *(const uint4*)(P + ((size_t)(b * NH + h)) * TS + r);
        const __half2* hp = (const __half2*)&v;
        #pragma unroll
        for (int j = 0; j < 4; j++) {
            float2 f = __half22float2(hp[j]);
            s[2*j] += f.x; s[2*j+1] += f.y;
        }
    }
    float4 o0 = make_float4(s[0], s[1], s[2], s[3]);
    float4 o1 = make_float4(s[4], s[5], s[6], s[7]);
    o0.x *= 0.0625f; o0.y *= 0.0625f; o0.z *= 0.0625f; o0.w *= 0.0625f;
    o1.x *= 0.0625f; o1.y *= 0.0625f; o1.z *= 0.0625f; o1.w *= 0.0625f;
    *(float4*)(out + base) = o0;
    *(float4*)(out + base + 4) = o1;
}

// ============================================================
// AV: C[b,t,h*64+d] = sum_s P[bh,t,s] * V[b,s,h*64+d]
// ============================================================
__global__ void __launch_bounds__(256) av_f16(
    const __half* __restrict__ P, const __half* __restrict__ V,
    __half* __restrict__ Cc)
{
    __shared__ __half Ps[128*72];
    __shared__ __half Vs[64*72];
    int tid = threadIdx.x, lane = tid & 31, wid = tid >> 5;
    int lr = lane >> 2, lc = lane & 3;
    int wm = (wid >> 1) * 32, wn = (wid & 1) * 32;
    int bh = blockIdx.y, b = bh >> 4, h = bh & 15;
    int t0 = blockIdx.x * 128;

    float acc[2][4][4];
    #pragma unroll
    for (int i = 0; i < 2; i++)
        #pragma unroll
        for (int j = 0; j < 4; j++)
            #pragma unroll
            for (int q = 0; q < 4; q++) acc[i][j][q] = 0.f;

    const __half* Pbase = P + ((size_t)bh * Tt + t0) * Ss;
    const __half* Vbase = V + (size_t)b * Ss * Hh + h * DK;

    for (int s0 = 0; s0 < Ss; s0 += 64) {
        #pragma unroll
        for (int j = 0; j < 4; j++) {
            int id = tid + j * 256;
            int r = id >> 3, c = (id & 7) * 8;
            *(uint4*)&Ps[r * 72 + c] = *(const uint4*)(Pbase + (size_t)r * Ss + s0 + c);
        }
        #pragma unroll
        for (int j = 0; j < 2; j++) {
            int id = tid + j * 256;
            int r = id >> 3, c = (id & 7) * 8;
            *(uint4*)&Vs[r * 72 + c] = *(const uint4*)(Vbase + (size_t)(s0 + r) * Hh + c);
        }
        __syncthreads();

        #pragma unroll
        for (int ks = 0; ks < 64; ks += 16) {
            uint32_t a[2][4], b2[4][2];
            #pragma unroll
            for (int im = 0; im < 2; im++) {
                int m = wm + im * 16;
                a[im][0] = *(uint32_t*)&Ps[(m + lr    ) * 72 + ks + 2*lc];
                a[im][1] = *(uint32_t*)&Ps[(m + lr + 8) * 72 + ks + 2*lc];
                a[im][2] = *(uint32_t*)&Ps[(m + lr    ) * 72 + ks + 8 + 2*lc];
                a[im][3] = *(uint32_t*)&Ps[(m + lr + 8) * 72 + ks + 8 + 2*lc];
            }
            ldB_pair(b2[0], b2[1], Vs, 72, ks, wn,      lane);
            ldB_pair(b2[2], b2[3], Vs, 72, ks, wn + 16, lane);
            #pragma unroll
            for (int im = 0; im < 2; im++)
                #pragma unroll
                for (int in_ = 0; in_ < 4; in_++)
                    mma_f16(acc[im][in_], a[im], b2[in_]);
        }
        __syncthreads();
    }

    #pragma unroll
    for (int im = 0; im < 2; im++) {
        #pragma unroll
        for (int in_ = 0; in_ < 4; in_++) {
            int r0 = t0 + wm + im * 16 + lr;
            int cb = wn + in_ * 8 + 2 * lc;
            *(__half2*)(Cc + (size_t)(b * Tt + r0) * Hh + h * DK + cb) =
                __floats2half2_rn(acc[im][in_][0], acc[im][in_][1]);
            *(__half2*)(Cc + (size_t)(b * Tt + r0 + 8) * Hh + h * DK + cb) =
                __floats2half2_rn(acc[im][in_][2], acc[im][in_][3]);
        }
    }
}

// ============================================================
extern "C" void kernel_launch(void* const* d_in, const int* in_sizes, int n_in,
                              void* d_out, int out_size)
{
    const float* hiddens = (const float*)d_in[0];
    const float* qh      = (const float*)d_in[1];
    const int*   mask    = (const int*)  d_in[2];
    const float* W_q     = (const float*)d_in[3];
    const float* b_q     = (const float*)d_in[4];
    const float* W_k     = (const float*)d_in[5];
    const float* W_v     = (const float*)d_in[6];
    const float* W_o     = (const float*)d_in[7];
    const float* b_o     = (const float*)d_in[8];
    float* out = (float*)d_out;

    __half *pH, *pQH, *pWq, *pWk, *pWv, *pWo, *pQ, *pK, *pV, *pP, *pC;
    cudaGetSymbolAddress((void**)&pH,  g_H);
    cudaGetSymbolAddress((void**)&pQH, g_QH);
    cudaGetSymbolAddress((void**)&pWq, g_Wq);
    cudaGetSymbolAddress((void**)&pWk, g_Wk);
    cudaGetSymbolAddress((void**)&pWv, g_Wv);
    cudaGetSymbolAddress((void**)&pWo, g_Wo);
    cudaGetSymbolAddress((void**)&pQ,  g_Q);
    cudaGetSymbolAddress((void**)&pK,  g_K);
    cudaGetSymbolAddress((void**)&pV,  g_V);
    cudaGetSymbolAddress((void**)&pP,  g_P);
    cudaGetSymbolAddress((void**)&pC,  g_C);

    const int GEMM_SMEM = (2*128*72 + 2*64*136) * 2;
    const int SS_SMEM   = (32*2056 + 2*128*72 + 32*72) * 2;
    cudaFuncSetAttribute(gemm16<true , true >, cudaFuncAttributeMaxDynamicSharedMemorySize, GEMM_SMEM);
    cudaFuncSetAttribute(gemm16<true , false>, cudaFuncAttributeMaxDynamicSharedMemorySize, GEMM_SMEM);
    cudaFuncSetAttribute(gemm16<false, true >, cudaFuncAttributeMaxDynamicSharedMemorySize, GEMM_SMEM);
    cudaFuncSetAttribute(scores_softmax, cudaFuncAttributeMaxDynamicSharedMemorySize, SS_SMEM);

    // fp32 -> fp16 converts
    f2h4<<<(Bb*Ss*Hh/4 + 255)/256, 256>>>(hiddens, pH,  Bb*Ss*Hh/4);
    f2h4<<<(Bb*Tt*Hh/4 + 255)/256, 256>>>(qh,      pQH, Bb*Tt*Hh/4);
    f2h4<<<(Hh*Hh/4 + 255)/256, 256>>>(W_q, pWq, Hh*Hh/4);
    f2h4<<<(Hh*Hh/4 + 255)/256, 256>>>(W_k, pWk, Hh*Hh/4);
    f2h4<<<(Hh*Hh/4 + 255)/256, 256>>>(W_v, pWv, Hh*Hh/4);
    f2h4<<<(Hh*Hh/4 + 255)/256, 256>>>(W_o, pWo, Hh*Hh/4);

    // Projections (Q gets 1/8 scale folded into epilogue)
    gemm16<true , true ><<<dim3(8, 32),  256, GEMM_SMEM>>>(pQH, pWq, b_q,     pQ, Bb*Tt, Hh, Hh, 0.125f);
    gemm16<true , false><<<dim3(8, 128), 256, GEMM_SMEM>>>(pH,  pWk, nullptr, pK, Bb*Ss, Hh, Hh, 1.0f);
    gemm16<true , false><<<dim3(8, 128), 256, GEMM_SMEM>>>(pH,  pWv, nullptr, pV, Bb*Ss, Hh, Hh, 1.0f);

    // Fused scores + softmax -> P (written once)
    scores_softmax<<<dim3(Tt/32, Bb*NH), 256, SS_SMEM>>>(pQ, pK, mask, pP);

    // Head-mean (second output region)
    {
        size_t n8 = (size_t)Bb * Tt * Ss / 8;
        mean_kernel<<<(unsigned)((n8 + 255) / 256), 256>>>(pP, out + (size_t)Bb*Tt*Hh);
    }

    // AV and output projection
    av_f16<<<dim3(Tt/128, Bb*NH), 256>>>(pP, pV, pC);
    gemm16<false, true ><<<dim3(8, 32), 256, GEMM_SMEM>>>(pC, pWo, b_o, out, Bb*Tt, Hh, Hh, 1.0f);
}